// round 1
// baseline (speedup 1.0000x reference)
#include <cuda_runtime.h>

#define NN 50000
#define EE 800000
#define NSLOPE 0.01f

// ---------------- scratch (device globals; no allocation allowed) ----------
__device__ float  g_hA[NN * 64];
__device__ float  g_hB[NN * 64];
__device__ float2 g_edge[EE];      // packed (src_as_float_bits, weight), dst-sorted
__device__ int    g_hist[NN];
__device__ int    g_cnt[NN];
__device__ int    g_row[NN + 1];

__device__ __forceinline__ float lrelu(float v) { return v >= 0.f ? v : NSLOPE * v; }

// ---------------- CSR build ------------------------------------------------
__global__ void zero_kernel() {
    int i = blockIdx.x * blockDim.x + threadIdx.x;
    if (i < NN) { g_hist[i] = 0; g_cnt[i] = 0; }
}

__global__ void hist_kernel(const int* __restrict__ ei) {
    int e = blockIdx.x * blockDim.x + threadIdx.x;
    if (e < EE) atomicAdd(&g_hist[ei[EE + e]], 1);
}

// single-block exclusive scan over 50000 bins (tiled Hillis-Steele)
__global__ void scan_kernel() {
    __shared__ int sh[1024];
    int carry = 0;
    for (int base = 0; base < NN; base += 1024) {
        int i = base + threadIdx.x;
        int v = (i < NN) ? g_hist[i] : 0;
        sh[threadIdx.x] = v;
        __syncthreads();
        for (int d = 1; d < 1024; d <<= 1) {
            int t = (threadIdx.x >= d) ? sh[threadIdx.x - d] : 0;
            __syncthreads();
            sh[threadIdx.x] += t;
            __syncthreads();
        }
        if (i < NN) g_row[i] = carry + sh[threadIdx.x] - v;   // exclusive
        carry += sh[1023];
        __syncthreads();
    }
    if (threadIdx.x == 0) g_row[NN] = carry;                  // == EE
}

__global__ void scatter_kernel(const int* __restrict__ ei, const float* __restrict__ ew) {
    int e = blockIdx.x * blockDim.x + threadIdx.x;
    if (e < EE) {
        int src = ei[e];
        int dst = ei[EE + e];
        int pos = g_row[dst] + atomicAdd(&g_cnt[dst], 1);
        g_edge[pos] = make_float2(__int_as_float(src), ew[e]);
    }
}

// ---------------- prep MLP: x[N,16] -> h[N,64] -----------------------------
// 256 threads = 4 nodes x 64 feature-threads
__global__ void prep_kernel(const float* __restrict__ x,
                            const float* __restrict__ Wpin, const float* __restrict__ bpin,
                            const float* __restrict__ Wph,  const float* __restrict__ bph) {
    __shared__ float sWin[16 * 64];
    __shared__ float sWh[64 * 64];
    __shared__ float sb0[64], sb1[64];
    __shared__ float sx[4][16];
    __shared__ float sh1[4][64];

    int tid = threadIdx.x;
    for (int i = tid; i < 16 * 64; i += 256) sWin[i] = Wpin[i];
    for (int i = tid; i < 64 * 64; i += 256) sWh[i]  = Wph[i];
    if (tid < 64) { sb0[tid] = bpin[tid]; sb1[tid] = bph[tid]; }

    int g = tid >> 6;          // node-in-block 0..3
    int j = tid & 63;          // feature
    int node = blockIdx.x * 4 + g;
    if (node < NN && j < 16) sx[g][j] = x[node * 16 + j];
    __syncthreads();

    if (node < NN) {
        float t = sb0[j];
        #pragma unroll
        for (int k = 0; k < 16; k++) t = fmaf(sx[g][k], sWin[k * 64 + j], t);
        sh1[g][j] = lrelu(t);
    }
    __syncthreads();
    if (node < NN) {
        float u = sb1[j];
        #pragma unroll
        for (int k = 0; k < 64; k++) u = fmaf(sh1[g][k], sWh[k * 64 + j], u);
        g_hA[node * 64 + j] = tanhf(u);
    }
}

// ---------------- fused GINEConv: aggregate + 2-layer MLP ------------------
// 256 threads = 8 warps, one node per warp
__global__ void conv_kernel(int dir,
                            const float* __restrict__ We_row, const float* __restrict__ be,
                            const float* __restrict__ Wm0,  const float* __restrict__ bm0,
                            const float* __restrict__ Wm1,  const float* __restrict__ bm1) {
    const float* __restrict__ hin  = dir ? g_hB : g_hA;
    float*       __restrict__ hout = dir ? g_hA : g_hB;

    __shared__ float sWm0[64 * 64];
    __shared__ float sWm1[64 * 64];
    __shared__ float sWe[64], sbe[64], sbm0[64], sbm1[64];
    __shared__ float zbuf[8][64];

    int tid = threadIdx.x;
    for (int i = tid; i < 64 * 64; i += 256) { sWm0[i] = Wm0[i]; sWm1[i] = Wm1[i]; }
    if (tid < 64) { sWe[tid] = We_row[tid]; sbe[tid] = be[tid];
                    sbm0[tid] = bm0[tid];   sbm1[tid] = bm1[tid]; }
    __syncthreads();

    int warp = tid >> 5;
    int lane = tid & 31;
    int node = blockIdx.x * 8 + warp;
    if (node >= NN) return;

    const float we0 = sWe[lane], we1 = sWe[lane + 32];
    const float eb0 = sbe[lane], eb1 = sbe[lane + 32];

    int rs = g_row[node];
    int re = g_row[node + 1];

    float acc0 = 0.f, acc1 = 0.f;
    for (int base = rs; base < re; base += 32) {
        int m = re - base; if (m > 32) m = 32;
        float2 ed = make_float2(0.f, 0.f);
        if (base + lane < re) ed = g_edge[base + lane];
        int   esrc = __float_as_int(ed.x);
        float ewt  = ed.y;
        for (int i = 0; i < m; i++) {
            int   s = __shfl_sync(0xffffffffu, esrc, i);
            float w = __shfl_sync(0xffffffffu, ewt,  i);
            float h0 = __ldg(&hin[s * 64 + lane]);
            float h1 = __ldg(&hin[s * 64 + lane + 32]);
            acc0 += fmaxf(fmaf(w, we0, eb0) + h0, 0.f);
            acc1 += fmaxf(fmaf(w, we1, eb1) + h1, 0.f);
        }
    }

    float z0 = acc0 + hin[node * 64 + lane];
    float z1 = acc1 + hin[node * 64 + lane + 32];
    zbuf[warp][lane]      = z0;
    zbuf[warp][lane + 32] = z1;
    __syncwarp();

    // MLP layer 0 + LeakyReLU
    float t0 = sbm0[lane], t1 = sbm0[lane + 32];
    #pragma unroll
    for (int i = 0; i < 64; i++) {
        float zi = zbuf[warp][i];
        t0 = fmaf(zi, sWm0[i * 64 + lane],      t0);
        t1 = fmaf(zi, sWm0[i * 64 + lane + 32], t1);
    }
    t0 = lrelu(t0); t1 = lrelu(t1);
    __syncwarp();
    zbuf[warp][lane]      = t0;
    zbuf[warp][lane + 32] = t1;
    __syncwarp();

    // MLP layer 1 + tanh
    float u0 = sbm1[lane], u1 = sbm1[lane + 32];
    #pragma unroll
    for (int i = 0; i < 64; i++) {
        float zi = zbuf[warp][i];
        u0 = fmaf(zi, sWm1[i * 64 + lane],      u0);
        u1 = fmaf(zi, sWm1[i * 64 + lane + 32], u1);
    }
    hout[node * 64 + lane]      = tanhf(u0);
    hout[node * 64 + lane + 32] = tanhf(u1);
}

// ---------------- post MLP: h[N,64] -> out[N,32] ---------------------------
// 256 threads = 4 nodes x 64 threads
__global__ void post_kernel(const float* __restrict__ Wq0, const float* __restrict__ bq0,
                            const float* __restrict__ Wq1, const float* __restrict__ bq1,
                            float* __restrict__ out) {
    __shared__ float sW0[64 * 64];
    __shared__ float sW1[64 * 32];
    __shared__ float sb0[64], sb1[32];
    __shared__ float sz[4][64];

    const float* __restrict__ hin = g_hB;   // after conv2 (A->B)

    int tid = threadIdx.x;
    for (int i = tid; i < 64 * 64; i += 256) sW0[i] = Wq0[i];
    for (int i = tid; i < 64 * 32; i += 256) sW1[i] = Wq1[i];
    if (tid < 64) sb0[tid] = bq0[tid];
    if (tid < 32) sb1[tid] = bq1[tid];
    __syncthreads();

    int g = tid >> 6;
    int j = tid & 63;
    int node = blockIdx.x * 4 + g;

    if (node < NN) {
        float t = sb0[j];
        const float* hr = &hin[node * 64];
        #pragma unroll
        for (int k = 0; k < 64; k++) t = fmaf(hr[k], sW0[k * 64 + j], t);
        sz[g][j] = lrelu(t);
    }
    __syncthreads();
    if (node < NN && j < 32) {
        float u = sb1[j];
        #pragma unroll
        for (int k = 0; k < 64; k++) u = fmaf(sz[g][k], sW1[k * 32 + j], u);
        out[node * 32 + j] = tanhf(u);
    }
}

// ---------------- launch ----------------------------------------------------
extern "C" void kernel_launch(void* const* d_in, const int* in_sizes, int n_in,
                              void* d_out, int out_size) {
    const float* x     = (const float*)d_in[0];
    const int*   ei    = (const int*)  d_in[1];
    const float* ew    = (const float*)d_in[2];
    const float* Wp_in = (const float*)d_in[3];
    const float* bp_in = (const float*)d_in[4];
    const float* Wp_h  = (const float*)d_in[5];
    const float* bp_h  = (const float*)d_in[6];
    const float* We    = (const float*)d_in[7];   // [3,1,64]
    const float* be    = (const float*)d_in[8];   // [3,64]
    const float* Wm0   = (const float*)d_in[9];   // [3,64,64]
    const float* bm0   = (const float*)d_in[10];
    const float* Wm1   = (const float*)d_in[11];
    const float* bm1   = (const float*)d_in[12];
    const float* Wq0   = (const float*)d_in[13];
    const float* bq0   = (const float*)d_in[14];
    const float* Wq1   = (const float*)d_in[15];  // [64,32]
    const float* bq1   = (const float*)d_in[16];
    float* out = (float*)d_out;

    // CSR build (per launch; graph-capturable, deterministic up to fp sum order)
    zero_kernel<<<(NN + 255) / 256, 256>>>();
    hist_kernel<<<(EE + 255) / 256, 256>>>(ei);
    scan_kernel<<<1, 1024>>>();
    scatter_kernel<<<(EE + 255) / 256, 256>>>(ei, ew);

    // prep MLP -> g_hA
    prep_kernel<<<(NN + 3) / 4, 256>>>(x, Wp_in, bp_in, Wp_h, bp_h);

    // 3 GINEConv layers, ping-pong A<->B
    int grid = (NN + 7) / 8;
    conv_kernel<<<grid, 256>>>(0, We + 0 * 64, be + 0 * 64,
                               Wm0 + 0 * 4096, bm0 + 0 * 64,
                               Wm1 + 0 * 4096, bm1 + 0 * 64);   // A -> B
    conv_kernel<<<grid, 256>>>(1, We + 1 * 64, be + 1 * 64,
                               Wm0 + 1 * 4096, bm0 + 1 * 64,
                               Wm1 + 1 * 4096, bm1 + 1 * 64);   // B -> A
    conv_kernel<<<grid, 256>>>(0, We + 2 * 64, be + 2 * 64,
                               Wm0 + 2 * 4096, bm0 + 2 * 64,
                               Wm1 + 2 * 4096, bm1 + 2 * 64);   // A -> B

    // post MLP -> out
    post_kernel<<<(NN + 3) / 4, 256>>>(Wq0, bq0, Wq1, bq1, out);
}

// round 2
// speedup vs baseline: 1.3388x; 1.3388x over previous
#include <cuda_runtime.h>

#define NN 50000
#define EE 800000
#define NSLOPE 0.01f
#define NB_SCAN ((NN + 1023) / 1024)      // 49

// ---------------- scratch (device globals; no allocation allowed) ----------
__device__ float  g_hA[NN * 64];
__device__ float  g_hB[NN * 64];
__device__ float2 g_edge[EE];      // (src_as_float_bits, weight), dst-grouped
__device__ int    g_hist[NN];
__device__ int    g_cnt[NN];
__device__ int    g_row[NN + 1];
__device__ int    g_bsum[64];

__device__ __forceinline__ float lrelu(float v) { return v >= 0.f ? v : NSLOPE * v; }

// ---------------- CSR build ------------------------------------------------
__global__ void zero_kernel() {
    int i = blockIdx.x * blockDim.x + threadIdx.x;
    if (i < NN) g_hist[i] = 0;
}

__global__ void hist_kernel(const int* __restrict__ ei) {
    int e = blockIdx.x * blockDim.x + threadIdx.x;
    if (e < EE) atomicAdd(&g_hist[ei[EE + e]], 1);
}

// level-1: per-1024-block exclusive scan + block totals; also zero g_cnt
__global__ void scan1_kernel() {
    __shared__ int wsum[32];
    int tid = threadIdx.x, lane = tid & 31, wid = tid >> 5;
    int i = blockIdx.x * 1024 + tid;
    int v = (i < NN) ? g_hist[i] : 0;
    if (i < NN) g_cnt[i] = 0;
    int x = v;
    #pragma unroll
    for (int d = 1; d < 32; d <<= 1) {
        int t = __shfl_up_sync(0xffffffffu, x, d);
        if (lane >= d) x += t;
    }
    if (lane == 31) wsum[wid] = x;
    __syncthreads();
    if (wid == 0) {
        int s = wsum[lane];
        #pragma unroll
        for (int d = 1; d < 32; d <<= 1) {
            int t = __shfl_up_sync(0xffffffffu, s, d);
            if (lane >= d) s += t;
        }
        wsum[lane] = s;
    }
    __syncthreads();
    int warpBase = (wid > 0) ? wsum[wid - 1] : 0;
    int excl = warpBase + x - v;
    if (i < NN) g_row[i] = excl;
    if (tid == 1023) g_bsum[blockIdx.x] = excl + v;   // block total
}

// level-2: exclusive scan of <=64 block totals (one block of 64 threads)
__global__ void scan2_kernel() {
    __shared__ int sh[64];
    int t = threadIdx.x;
    int v = (t < NB_SCAN) ? g_bsum[t] : 0;
    sh[t] = v;
    __syncthreads();
    #pragma unroll
    for (int d = 1; d < 64; d <<= 1) {
        int u = (t >= d) ? sh[t - d] : 0;
        __syncthreads();
        sh[t] += u;
        __syncthreads();
    }
    if (t < NB_SCAN) g_bsum[t] = sh[t] - v;           // exclusive
}

// level-3: add block offsets
__global__ void scan3_kernel() {
    int i = blockIdx.x * blockDim.x + threadIdx.x;
    if (i < NN) g_row[i] += g_bsum[i >> 10];
    if (i == 0) g_row[NN] = EE;
}

__global__ void scatter_kernel(const int* __restrict__ ei, const float* __restrict__ ew) {
    int e = blockIdx.x * blockDim.x + threadIdx.x;
    if (e < EE) {
        int src = ei[e];
        int dst = ei[EE + e];
        int pos = g_row[dst] + atomicAdd(&g_cnt[dst], 1);
        g_edge[pos] = make_float2(__int_as_float(src), ew[e]);
    }
}

// ---------------- prep MLP: x[N,16] -> h[N,64] -----------------------------
// persistent blocks: 256 threads = 4 nodes x 64 feature-threads per iteration
__global__ void prep_kernel(const float* __restrict__ x,
                            const float* __restrict__ Wpin, const float* __restrict__ bpin,
                            const float* __restrict__ Wph,  const float* __restrict__ bph) {
    __shared__ float sWin[16 * 64];
    __shared__ float sWh[64 * 64];
    __shared__ float sb0[64], sb1[64];
    __shared__ float sx[4][16];
    __shared__ float sh1[4][64];

    int tid = threadIdx.x;
    for (int i = tid; i < 16 * 64; i += 256) sWin[i] = Wpin[i];
    for (int i = tid; i < 64 * 64; i += 256) sWh[i]  = Wph[i];
    if (tid < 64) { sb0[tid] = bpin[tid]; sb1[tid] = bph[tid]; }
    __syncthreads();

    int g = tid >> 6, j = tid & 63;
    int ngroups = (NN + 3) / 4;
    for (int grp = blockIdx.x; grp < ngroups; grp += gridDim.x) {
        int node = grp * 4 + g;
        if (node < NN && j < 16) sx[g][j] = x[node * 16 + j];
        __syncthreads();
        if (node < NN) {
            float t = sb0[j];
            #pragma unroll
            for (int k = 0; k < 16; k++) t = fmaf(sx[g][k], sWin[k * 64 + j], t);
            sh1[g][j] = lrelu(t);
        }
        __syncthreads();
        if (node < NN) {
            float u = sb1[j];
            #pragma unroll
            for (int k = 0; k < 64; k++) u = fmaf(sh1[g][k], sWh[k * 64 + j], u);
            g_hA[node * 64 + j] = tanhf(u);
        }
        __syncthreads();
    }
}

// ---------------- fused GINEConv: aggregate + 2-layer MLP ------------------
// persistent: 256 threads = 8 warps; each warp strides over nodes
__global__ void conv_kernel(int dir,
                            const float* __restrict__ We_row, const float* __restrict__ be,
                            const float* __restrict__ Wm0,  const float* __restrict__ bm0,
                            const float* __restrict__ Wm1,  const float* __restrict__ bm1) {
    const float*  hin  = dir ? g_hB : g_hA;
    float*        hout = dir ? g_hA : g_hB;
    const float2* __restrict__ hin2  = (const float2*)hin;
    float2*       __restrict__ hout2 = (float2*)hout;

    __shared__ float sWm0[64 * 64];
    __shared__ float sWm1[64 * 64];
    __shared__ float sWe[64], sbe[64], sbm0[64], sbm1[64];
    __shared__ float zbuf[8][64];

    int tid = threadIdx.x;
    for (int i = tid; i < 64 * 64; i += 256) { sWm0[i] = Wm0[i]; sWm1[i] = Wm1[i]; }
    if (tid < 64) { sWe[tid] = We_row[tid]; sbe[tid] = be[tid];
                    sbm0[tid] = bm0[tid];   sbm1[tid] = bm1[tid]; }
    __syncthreads();

    int warp = tid >> 5, lane = tid & 31;
    const float2* sWm0v = (const float2*)sWm0;
    const float2* sWm1v = (const float2*)sWm1;
    const float wex = sWe[2 * lane],  wey = sWe[2 * lane + 1];
    const float bex = sbe[2 * lane],  bey = sbe[2 * lane + 1];
    const float b0x = sbm0[2 * lane], b0y = sbm0[2 * lane + 1];
    const float b1x = sbm1[2 * lane], b1y = sbm1[2 * lane + 1];

    int warpStride = gridDim.x * 8;
    for (int node = blockIdx.x * 8 + warp; node < NN; node += warpStride) {
        int rs = g_row[node];
        int re = g_row[node + 1];

        float accx = 0.f, accy = 0.f;
        for (int base = rs; base < re; base += 32) {
            int m = re - base; if (m > 32) m = 32;
            float2 ed = make_float2(0.f, 0.f);
            if (base + lane < re) ed = __ldg(&g_edge[base + lane]);
            int   esrc = __float_as_int(ed.x);
            float ewt  = ed.y;
            for (int i = 0; i < m; i++) {
                int   s = __shfl_sync(0xffffffffu, esrc, i);
                float w = __shfl_sync(0xffffffffu, ewt,  i);
                float2 h = __ldg(&hin2[s * 32 + lane]);
                accx += fmaxf(fmaf(w, wex, bex) + h.x, 0.f);
                accy += fmaxf(fmaf(w, wey, bey) + h.y, 0.f);
            }
        }

        float2 hself = hin2[node * 32 + lane];
        zbuf[warp][2 * lane]     = accx + hself.x;
        zbuf[warp][2 * lane + 1] = accy + hself.y;
        __syncwarp();

        // MLP layer 0 + LeakyReLU
        float t0 = b0x, t1 = b0y;
        #pragma unroll
        for (int i = 0; i < 64; i++) {
            float zi = zbuf[warp][i];
            float2 wv = sWm0v[i * 32 + lane];
            t0 = fmaf(zi, wv.x, t0);
            t1 = fmaf(zi, wv.y, t1);
        }
        t0 = lrelu(t0); t1 = lrelu(t1);
        __syncwarp();
        zbuf[warp][2 * lane]     = t0;
        zbuf[warp][2 * lane + 1] = t1;
        __syncwarp();

        // MLP layer 1 + tanh
        float u0 = b1x, u1 = b1y;
        #pragma unroll
        for (int i = 0; i < 64; i++) {
            float zi = zbuf[warp][i];
            float2 wv = sWm1v[i * 32 + lane];
            u0 = fmaf(zi, wv.x, u0);
            u1 = fmaf(zi, wv.y, u1);
        }
        hout2[node * 32 + lane] = make_float2(tanhf(u0), tanhf(u1));
    }
}

// ---------------- post MLP: h[N,64] -> out[N,32] ---------------------------
__global__ void post_kernel(const float* __restrict__ Wq0, const float* __restrict__ bq0,
                            const float* __restrict__ Wq1, const float* __restrict__ bq1,
                            float* __restrict__ out) {
    __shared__ float sW0[64 * 64];
    __shared__ float sW1[64 * 32];
    __shared__ float sb0[64], sb1[32];
    __shared__ float sz[4][64];

    const float* __restrict__ hin = g_hB;   // after conv2 (A->B)

    int tid = threadIdx.x;
    for (int i = tid; i < 64 * 64; i += 256) sW0[i] = Wq0[i];
    for (int i = tid; i < 64 * 32; i += 256) sW1[i] = Wq1[i];
    if (tid < 64) sb0[tid] = bq0[tid];
    if (tid < 32) sb1[tid] = bq1[tid];
    __syncthreads();

    int g = tid >> 6, j = tid & 63;
    int ngroups = (NN + 3) / 4;
    for (int grp = blockIdx.x; grp < ngroups; grp += gridDim.x) {
        int node = grp * 4 + g;
        if (node < NN) {
            float t = sb0[j];
            const float* hr = &hin[node * 64];
            #pragma unroll
            for (int k = 0; k < 64; k++) t = fmaf(hr[k], sW0[k * 64 + j], t);
            sz[g][j] = lrelu(t);
        }
        __syncthreads();
        if (node < NN && j < 32) {
            float u = sb1[j];
            #pragma unroll
            for (int k = 0; k < 64; k++) u = fmaf(sz[g][k], sW1[k * 32 + j], u);
            out[node * 32 + j] = tanhf(u);
        }
        __syncthreads();
    }
}

// ---------------- launch ----------------------------------------------------
extern "C" void kernel_launch(void* const* d_in, const int* in_sizes, int n_in,
                              void* d_out, int out_size) {
    const float* x     = (const float*)d_in[0];
    const int*   ei    = (const int*)  d_in[1];
    const float* ew    = (const float*)d_in[2];
    const float* Wp_in = (const float*)d_in[3];
    const float* bp_in = (const float*)d_in[4];
    const float* Wp_h  = (const float*)d_in[5];
    const float* bp_h  = (const float*)d_in[6];
    const float* We    = (const float*)d_in[7];
    const float* be    = (const float*)d_in[8];
    const float* Wm0   = (const float*)d_in[9];
    const float* bm0   = (const float*)d_in[10];
    const float* Wm1   = (const float*)d_in[11];
    const float* bm1   = (const float*)d_in[12];
    const float* Wq0   = (const float*)d_in[13];
    const float* bq0   = (const float*)d_in[14];
    const float* Wq1   = (const float*)d_in[15];
    const float* bq1   = (const float*)d_in[16];
    float* out = (float*)d_out;

    // CSR build
    zero_kernel<<<(NN + 255) / 256, 256>>>();
    hist_kernel<<<(EE + 255) / 256, 256>>>(ei);
    scan1_kernel<<<NB_SCAN, 1024>>>();
    scan2_kernel<<<1, 64>>>();
    scan3_kernel<<<(NN + 255) / 256, 256>>>();
    scatter_kernel<<<(EE + 255) / 256, 256>>>(ei, ew);

    // prep MLP -> g_hA  (persistent blocks)
    prep_kernel<<<592, 256>>>(x, Wp_in, bp_in, Wp_h, bp_h);

    // 3 GINEConv layers, ping-pong A<->B (persistent blocks)
    conv_kernel<<<592, 256>>>(0, We + 0 * 64, be + 0 * 64,
                              Wm0 + 0 * 4096, bm0 + 0 * 64,
                              Wm1 + 0 * 4096, bm1 + 0 * 64);   // A -> B
    conv_kernel<<<592, 256>>>(1, We + 1 * 64, be + 1 * 64,
                              Wm0 + 1 * 4096, bm0 + 1 * 64,
                              Wm1 + 1 * 4096, bm1 + 1 * 64);   // B -> A
    conv_kernel<<<592, 256>>>(0, We + 2 * 64, be + 2 * 64,
                              Wm0 + 2 * 4096, bm0 + 2 * 64,
                              Wm1 + 2 * 4096, bm1 + 2 * 64);   // A -> B

    // post MLP -> out
    post_kernel<<<592, 256>>>(Wq0, bq0, Wq1, bq1, out);
}

// round 3
// speedup vs baseline: 2.1727x; 1.6229x over previous
#include <cuda_runtime.h>

#define NN 50000
#define EE 800000
#define NSLOPE 0.01f
#define NB_SCAN ((NN + 1023) / 1024)      // 49
#define NGROUPS ((NN + 7) / 8)            // 6250

// ---------------- scratch (device globals; no allocation allowed) ----------
__device__ float  g_hA[NN * 64];
__device__ float  g_hB[NN * 64];
__device__ float2 g_edge[EE];      // (src_as_float_bits, weight), dst-grouped
__device__ int    g_hist[NN];
__device__ int    g_cnt[NN];
__device__ int    g_row[NN + 1];
__device__ int    g_bsum[64];

__device__ __forceinline__ float lrelu(float v) { return v >= 0.f ? v : NSLOPE * v; }

// ---------------- CSR build ------------------------------------------------
__global__ void zero_kernel() {
    int i = blockIdx.x * blockDim.x + threadIdx.x;
    if (i < NN) g_hist[i] = 0;
}

__global__ void hist_kernel(const int* __restrict__ ei) {
    int e = blockIdx.x * blockDim.x + threadIdx.x;
    if (e < EE) atomicAdd(&g_hist[ei[EE + e]], 1);
}

__global__ void scan1_kernel() {
    __shared__ int wsum[32];
    int tid = threadIdx.x, lane = tid & 31, wid = tid >> 5;
    int i = blockIdx.x * 1024 + tid;
    int v = (i < NN) ? g_hist[i] : 0;
    if (i < NN) g_cnt[i] = 0;
    int x = v;
    #pragma unroll
    for (int d = 1; d < 32; d <<= 1) {
        int t = __shfl_up_sync(0xffffffffu, x, d);
        if (lane >= d) x += t;
    }
    if (lane == 31) wsum[wid] = x;
    __syncthreads();
    if (wid == 0) {
        int s = wsum[lane];
        #pragma unroll
        for (int d = 1; d < 32; d <<= 1) {
            int t = __shfl_up_sync(0xffffffffu, s, d);
            if (lane >= d) s += t;
        }
        wsum[lane] = s;
    }
    __syncthreads();
    int warpBase = (wid > 0) ? wsum[wid - 1] : 0;
    int excl = warpBase + x - v;
    if (i < NN) g_row[i] = excl;
    if (tid == 1023) g_bsum[blockIdx.x] = excl + v;
}

__global__ void scan2_kernel() {
    __shared__ int sh[64];
    int t = threadIdx.x;
    int v = (t < NB_SCAN) ? g_bsum[t] : 0;
    sh[t] = v;
    __syncthreads();
    #pragma unroll
    for (int d = 1; d < 64; d <<= 1) {
        int u = (t >= d) ? sh[t - d] : 0;
        __syncthreads();
        sh[t] += u;
        __syncthreads();
    }
    if (t < NB_SCAN) g_bsum[t] = sh[t] - v;
}

__global__ void scan3_kernel() {
    int i = blockIdx.x * blockDim.x + threadIdx.x;
    if (i < NN) g_row[i] += g_bsum[i >> 10];
    if (i == 0) g_row[NN] = EE;
}

__global__ void scatter_kernel(const int* __restrict__ ei, const float* __restrict__ ew) {
    int e = blockIdx.x * blockDim.x + threadIdx.x;
    if (e < EE) {
        int src = ei[e];
        int dst = ei[EE + e];
        int pos = g_row[dst] + atomicAdd(&g_cnt[dst], 1);
        g_edge[pos] = make_float2(__int_as_float(src), ew[e]);
    }
}

// ---------------- prep MLP: x[N,16] -> h[N,64], warp = 8 nodes -------------
__global__ void prep_kernel(const float* __restrict__ x,
                            const float* __restrict__ Wpin, const float* __restrict__ bpin,
                            const float* __restrict__ Wph,  const float* __restrict__ bph) {
    __shared__ float sWin[16 * 64];
    __shared__ float sWh[64 * 64];
    __shared__ float sb0[64], sb1[64];
    __shared__ float xs[8][8][16];
    __shared__ float zs[8][8][64];

    int tid = threadIdx.x;
    for (int i = tid; i < 16 * 64; i += 256) sWin[i] = Wpin[i];
    for (int i = tid; i < 64 * 64; i += 256) sWh[i]  = Wph[i];
    if (tid < 64) { sb0[tid] = bpin[tid]; sb1[tid] = bph[tid]; }
    __syncthreads();

    int warp = tid >> 5, lane = tid & 31;
    const float2* sWinV = (const float2*)sWin;
    const float2* sWhV  = (const float2*)sWh;
    float2* hout2 = (float2*)g_hA;
    const float2 b0 = ((const float2*)sb0)[lane];
    const float2 b1 = ((const float2*)sb1)[lane];

    for (int grp = blockIdx.x * 8 + warp; grp < NGROUPS; grp += gridDim.x * 8) {
        int nbase = grp * 8;
        int vn = NN - nbase; if (vn > 8) vn = 8;
        // stage x: 8 nodes x 16 floats = 128 contiguous floats
        if (4 * lane < vn * 16) {
            float4 v = *(const float4*)&x[nbase * 16 + 4 * lane];
            *(float4*)&xs[warp][lane >> 2][(4 * lane) & 15] = v;
        }
        __syncwarp();
        // layer 0: 16 -> 64
        float2 t[8];
        #pragma unroll
        for (int n = 0; n < 8; n++) t[n] = b0;
        #pragma unroll
        for (int k = 0; k < 16; k++) {
            float2 wv = sWinV[k * 32 + lane];
            #pragma unroll
            for (int n = 0; n < 8; n++) {
                float zk = xs[warp][n][k];
                t[n].x = fmaf(zk, wv.x, t[n].x);
                t[n].y = fmaf(zk, wv.y, t[n].y);
            }
        }
        #pragma unroll
        for (int n = 0; n < 8; n++)
            ((float2*)zs[warp][n])[lane] = make_float2(lrelu(t[n].x), lrelu(t[n].y));
        __syncwarp();
        // layer 1: 64 -> 64
        float2 u[8];
        #pragma unroll
        for (int n = 0; n < 8; n++) u[n] = b1;
        #pragma unroll
        for (int k = 0; k < 64; k++) {
            float2 wv = sWhV[k * 32 + lane];
            #pragma unroll
            for (int n = 0; n < 8; n++) {
                float zk = zs[warp][n][k];
                u[n].x = fmaf(zk, wv.x, u[n].x);
                u[n].y = fmaf(zk, wv.y, u[n].y);
            }
        }
        #pragma unroll
        for (int n = 0; n < 8; n++) {
            int node = nbase + n;
            if (node < NN)
                hout2[node * 32 + lane] = make_float2(tanhf(u[n].x), tanhf(u[n].y));
        }
        __syncwarp();
    }
}

// ---------------- fused GINEConv: aggregate + batched 2-layer MLP ----------
// 256 threads = 8 warps; each warp processes groups of 8 nodes
__global__ void conv_kernel(int dir,
                            const float* __restrict__ We_row, const float* __restrict__ be,
                            const float* __restrict__ Wm0,  const float* __restrict__ bm0,
                            const float* __restrict__ Wm1,  const float* __restrict__ bm1) {
    const float*  hin  = dir ? g_hB : g_hA;
    float*        hout = dir ? g_hA : g_hB;
    const float4* __restrict__ hin4  = (const float4*)hin;
    float2*       __restrict__ hout2 = (float2*)hout;

    __shared__ float sWm0[64 * 64];
    __shared__ float sWm1[64 * 64];
    __shared__ float sWe[64], sbe[64], sbm0[64], sbm1[64];
    __shared__ float zs[8][8][64];

    int tid = threadIdx.x;
    for (int i = tid; i < 64 * 64; i += 256) { sWm0[i] = Wm0[i]; sWm1[i] = Wm1[i]; }
    if (tid < 64) { sWe[tid] = We_row[tid]; sbe[tid] = be[tid];
                    sbm0[tid] = bm0[tid];   sbm1[tid] = bm1[tid]; }
    __syncthreads();

    int warp = tid >> 5, lane = tid & 31;
    int u16 = lane >> 4, c = lane & 15;           // half-warp id, feature quad
    const float2* sWm0v = (const float2*)sWm0;
    const float2* sWm1v = (const float2*)sWm1;
    const float4 we4 = *(const float4*)&sWe[4 * c];
    const float4 be4 = *(const float4*)&sbe[4 * c];
    const float2 b0  = ((const float2*)sbm0)[lane];
    const float2 b1  = ((const float2*)sbm1)[lane];

    for (int grp = blockIdx.x * 8 + warp; grp < NGROUPS; grp += gridDim.x * 8) {
        int nbase = grp * 8;
        // ---- aggregation for 8 nodes ----
        #pragma unroll 1
        for (int n = 0; n < 8; n++) {
            int node = nbase + n;
            if (node < NN) {
                int rs = g_row[node];
                int re = g_row[node + 1];
                float4 acc = make_float4(0.f, 0.f, 0.f, 0.f);
                for (int base = rs; base < re; base += 32) {
                    int m = re - base; if (m > 32) m = 32;
                    float2 ed = make_float2(0.f, 0.f);
                    if (base + lane < re) ed = __ldg(&g_edge[base + lane]);
                    int   esrc = __float_as_int(ed.x);
                    float ewt  = ed.y;
                    int i = 0;
                    for (; i + 4 <= m; i += 4) {
                        int sA = __shfl_sync(0xffffffffu, esrc, i + u16);
                        float wA = __shfl_sync(0xffffffffu, ewt, i + u16);
                        int sB = __shfl_sync(0xffffffffu, esrc, i + 2 + u16);
                        float wB = __shfl_sync(0xffffffffu, ewt, i + 2 + u16);
                        float4 hA = __ldg(&hin4[sA * 16 + c]);
                        float4 hB = __ldg(&hin4[sB * 16 + c]);
                        acc.x += fmaxf(hA.x + fmaf(wA, we4.x, be4.x), 0.f);
                        acc.y += fmaxf(hA.y + fmaf(wA, we4.y, be4.y), 0.f);
                        acc.z += fmaxf(hA.z + fmaf(wA, we4.z, be4.z), 0.f);
                        acc.w += fmaxf(hA.w + fmaf(wA, we4.w, be4.w), 0.f);
                        acc.x += fmaxf(hB.x + fmaf(wB, we4.x, be4.x), 0.f);
                        acc.y += fmaxf(hB.y + fmaf(wB, we4.y, be4.y), 0.f);
                        acc.z += fmaxf(hB.z + fmaf(wB, we4.z, be4.z), 0.f);
                        acc.w += fmaxf(hB.w + fmaf(wB, we4.w, be4.w), 0.f);
                    }
                    for (; i < m; i += 2) {
                        int idx = i + u16;
                        int   s = __shfl_sync(0xffffffffu, esrc, idx & 31);
                        float w = __shfl_sync(0xffffffffu, ewt,  idx & 31);
                        if (idx < m) {
                            float4 h = __ldg(&hin4[s * 16 + c]);
                            acc.x += fmaxf(h.x + fmaf(w, we4.x, be4.x), 0.f);
                            acc.y += fmaxf(h.y + fmaf(w, we4.y, be4.y), 0.f);
                            acc.z += fmaxf(h.z + fmaf(w, we4.z, be4.z), 0.f);
                            acc.w += fmaxf(h.w + fmaf(w, we4.w, be4.w), 0.f);
                        }
                    }
                }
                // combine the two half-warps
                acc.x += __shfl_xor_sync(0xffffffffu, acc.x, 16);
                acc.y += __shfl_xor_sync(0xffffffffu, acc.y, 16);
                acc.z += __shfl_xor_sync(0xffffffffu, acc.z, 16);
                acc.w += __shfl_xor_sync(0xffffffffu, acc.w, 16);
                if (u16 == 0) {
                    float4 hs = __ldg(&hin4[node * 16 + c]);
                    acc.x += hs.x; acc.y += hs.y; acc.z += hs.z; acc.w += hs.w;
                    *(float4*)&zs[warp][n][4 * c] = acc;
                }
            } else if (u16 == 0) {
                *(float4*)&zs[warp][n][4 * c] = make_float4(0.f, 0.f, 0.f, 0.f);
            }
        }
        __syncwarp();

        // ---- MLP layer 0 (64->64) + LeakyReLU, batched over 8 nodes ----
        float2 t[8];
        #pragma unroll
        for (int n = 0; n < 8; n++) t[n] = b0;
        #pragma unroll
        for (int k = 0; k < 64; k++) {
            float2 wv = sWm0v[k * 32 + lane];
            #pragma unroll
            for (int n = 0; n < 8; n++) {
                float zk = zs[warp][n][k];
                t[n].x = fmaf(zk, wv.x, t[n].x);
                t[n].y = fmaf(zk, wv.y, t[n].y);
            }
        }
        __syncwarp();
        #pragma unroll
        for (int n = 0; n < 8; n++)
            ((float2*)zs[warp][n])[lane] = make_float2(lrelu(t[n].x), lrelu(t[n].y));
        __syncwarp();

        // ---- MLP layer 1 (64->64) + tanh ----
        float2 uo[8];
        #pragma unroll
        for (int n = 0; n < 8; n++) uo[n] = b1;
        #pragma unroll
        for (int k = 0; k < 64; k++) {
            float2 wv = sWm1v[k * 32 + lane];
            #pragma unroll
            for (int n = 0; n < 8; n++) {
                float zk = zs[warp][n][k];
                uo[n].x = fmaf(zk, wv.x, uo[n].x);
                uo[n].y = fmaf(zk, wv.y, uo[n].y);
            }
        }
        #pragma unroll
        for (int n = 0; n < 8; n++) {
            int node = nbase + n;
            if (node < NN)
                hout2[node * 32 + lane] = make_float2(tanhf(uo[n].x), tanhf(uo[n].y));
        }
        __syncwarp();
    }
}

// ---------------- post MLP: h[N,64] -> out[N,32], warp = 8 nodes -----------
__global__ void post_kernel(const float* __restrict__ Wq0, const float* __restrict__ bq0,
                            const float* __restrict__ Wq1, const float* __restrict__ bq1,
                            float* __restrict__ out) {
    __shared__ float sW0[64 * 64];
    __shared__ float sW1[64 * 32];
    __shared__ float sb0[64], sb1[32];
    __shared__ float zs[8][8][64];

    const float2* __restrict__ hin2 = (const float2*)g_hB;   // after conv2

    int tid = threadIdx.x;
    for (int i = tid; i < 64 * 64; i += 256) sW0[i] = Wq0[i];
    for (int i = tid; i < 64 * 32; i += 256) sW1[i] = Wq1[i];
    if (tid < 64) sb0[tid] = bq0[tid];
    if (tid < 32) sb1[tid] = bq1[tid];
    __syncthreads();

    int warp = tid >> 5, lane = tid & 31;
    const float2* sW0v = (const float2*)sW0;
    const float2 b0 = ((const float2*)sb0)[lane];
    const float b1l = sb1[lane];

    for (int grp = blockIdx.x * 8 + warp; grp < NGROUPS; grp += gridDim.x * 8) {
        int nbase = grp * 8;
        #pragma unroll
        for (int n = 0; n < 8; n++) {
            int node = nbase + n;
            float2 v = (node < NN) ? hin2[node * 32 + lane] : make_float2(0.f, 0.f);
            ((float2*)zs[warp][n])[lane] = v;
        }
        __syncwarp();
        // layer 0: 64 -> 64 + lrelu
        float2 t[8];
        #pragma unroll
        for (int n = 0; n < 8; n++) t[n] = b0;
        #pragma unroll
        for (int k = 0; k < 64; k++) {
            float2 wv = sW0v[k * 32 + lane];
            #pragma unroll
            for (int n = 0; n < 8; n++) {
                float zk = zs[warp][n][k];
                t[n].x = fmaf(zk, wv.x, t[n].x);
                t[n].y = fmaf(zk, wv.y, t[n].y);
            }
        }
        __syncwarp();
        #pragma unroll
        for (int n = 0; n < 8; n++)
            ((float2*)zs[warp][n])[lane] = make_float2(lrelu(t[n].x), lrelu(t[n].y));
        __syncwarp();
        // layer 1: 64 -> 32 + tanh
        float a[8];
        #pragma unroll
        for (int n = 0; n < 8; n++) a[n] = b1l;
        #pragma unroll
        for (int k = 0; k < 64; k++) {
            float wk = sW1[k * 32 + lane];
            #pragma unroll
            for (int n = 0; n < 8; n++)
                a[n] = fmaf(zs[warp][n][k], wk, a[n]);
        }
        #pragma unroll
        for (int n = 0; n < 8; n++) {
            int node = nbase + n;
            if (node < NN) out[node * 32 + lane] = tanhf(a[n]);
        }
        __syncwarp();
    }
}

// ---------------- launch ----------------------------------------------------
extern "C" void kernel_launch(void* const* d_in, const int* in_sizes, int n_in,
                              void* d_out, int out_size) {
    const float* x     = (const float*)d_in[0];
    const int*   ei    = (const int*)  d_in[1];
    const float* ew    = (const float*)d_in[2];
    const float* Wp_in = (const float*)d_in[3];
    const float* bp_in = (const float*)d_in[4];
    const float* Wp_h  = (const float*)d_in[5];
    const float* bp_h  = (const float*)d_in[6];
    const float* We    = (const float*)d_in[7];
    const float* be    = (const float*)d_in[8];
    const float* Wm0   = (const float*)d_in[9];
    const float* bm0   = (const float*)d_in[10];
    const float* Wm1   = (const float*)d_in[11];
    const float* bm1   = (const float*)d_in[12];
    const float* Wq0   = (const float*)d_in[13];
    const float* bq0   = (const float*)d_in[14];
    const float* Wq1   = (const float*)d_in[15];
    const float* bq1   = (const float*)d_in[16];
    float* out = (float*)d_out;

    // CSR build
    zero_kernel<<<(NN + 255) / 256, 256>>>();
    hist_kernel<<<(EE + 255) / 256, 256>>>(ei);
    scan1_kernel<<<NB_SCAN, 1024>>>();
    scan2_kernel<<<1, 64>>>();
    scan3_kernel<<<(NN + 255) / 256, 256>>>();
    scatter_kernel<<<(EE + 255) / 256, 256>>>(ei, ew);

    // prep MLP -> g_hA
    prep_kernel<<<592, 256>>>(x, Wp_in, bp_in, Wp_h, bp_h);

    // 3 GINEConv layers, ping-pong A<->B
    conv_kernel<<<592, 256>>>(0, We + 0 * 64, be + 0 * 64,
                              Wm0 + 0 * 4096, bm0 + 0 * 64,
                              Wm1 + 0 * 4096, bm1 + 0 * 64);   // A -> B
    conv_kernel<<<592, 256>>>(1, We + 1 * 64, be + 1 * 64,
                              Wm0 + 1 * 4096, bm0 + 1 * 64,
                              Wm1 + 1 * 4096, bm1 + 1 * 64);   // B -> A
    conv_kernel<<<592, 256>>>(0, We + 2 * 64, be + 2 * 64,
                              Wm0 + 2 * 4096, bm0 + 2 * 64,
                              Wm1 + 2 * 4096, bm1 + 2 * 64);   // A -> B

    // post MLP -> out
    post_kernel<<<592, 256>>>(Wq0, bq0, Wq1, bq1, out);
}

// round 4
// speedup vs baseline: 2.3181x; 1.0669x over previous
#include <cuda_runtime.h>

#define NN 50000
#define EE 800000
#define NSLOPE 0.01f
#define NB_SCAN ((NN + 1023) / 1024)      // 49
#define NGROUPS (NN / 8)                  // 6250 (NN % 8 == 0)
#define ZP 10                             // padded row stride for transposed z

typedef unsigned long long u64;

// ---------------- scratch ----------------------------------------------------
__device__ float  g_hA[NN * 64];
__device__ float  g_hB[NN * 64];
__device__ float2 g_edge[EE];
__device__ int    g_hist[NN];
__device__ int    g_cnt[NN];
__device__ int    g_row[NN + 1];
__device__ int    g_bsum[64];
__device__ int    g_work[8];              // work-stealing counters

__device__ __forceinline__ float lrelu(float v) { return v >= 0.f ? v : NSLOPE * v; }

__device__ __forceinline__ u64 pk(float a, float b) {
    u64 r; asm("mov.b64 %0,{%1,%2};" : "=l"(r) : "f"(a), "f"(b)); return r;
}
__device__ __forceinline__ void upk(u64 v, float& a, float& b) {
    asm("mov.b64 {%0,%1},%2;" : "=f"(a), "=f"(b) : "l"(v));
}
__device__ __forceinline__ u64 ffma2(u64 a, u64 b, u64 c) {
    u64 d; asm("fma.rn.f32x2 %0,%1,%2,%3;" : "=l"(d) : "l"(a), "l"(b), "l"(c)); return d;
}

// ---------------- CSR build --------------------------------------------------
__global__ void zero_kernel() {
    int i = blockIdx.x * blockDim.x + threadIdx.x;
    if (i < NN) g_hist[i] = 0;
    if (i < 8)  g_work[i] = 0;
}

__global__ void hist_kernel(const int* __restrict__ ei) {
    int e = blockIdx.x * blockDim.x + threadIdx.x;
    if (e < EE) atomicAdd(&g_hist[ei[EE + e]], 1);
}

__global__ void scan1_kernel() {
    __shared__ int wsum[32];
    int tid = threadIdx.x, lane = tid & 31, wid = tid >> 5;
    int i = blockIdx.x * 1024 + tid;
    int v = (i < NN) ? g_hist[i] : 0;
    if (i < NN) g_cnt[i] = 0;
    int x = v;
    #pragma unroll
    for (int d = 1; d < 32; d <<= 1) {
        int t = __shfl_up_sync(0xffffffffu, x, d);
        if (lane >= d) x += t;
    }
    if (lane == 31) wsum[wid] = x;
    __syncthreads();
    if (wid == 0) {
        int s = wsum[lane];
        #pragma unroll
        for (int d = 1; d < 32; d <<= 1) {
            int t = __shfl_up_sync(0xffffffffu, s, d);
            if (lane >= d) s += t;
        }
        wsum[lane] = s;
    }
    __syncthreads();
    int warpBase = (wid > 0) ? wsum[wid - 1] : 0;
    int excl = warpBase + x - v;
    if (i < NN) g_row[i] = excl;
    if (tid == 1023) g_bsum[blockIdx.x] = excl + v;
}

__global__ void scan2_kernel() {
    __shared__ int sh[64];
    int t = threadIdx.x;
    int v = (t < NB_SCAN) ? g_bsum[t] : 0;
    sh[t] = v;
    __syncthreads();
    #pragma unroll
    for (int d = 1; d < 64; d <<= 1) {
        int u = (t >= d) ? sh[t - d] : 0;
        __syncthreads();
        sh[t] += u;
        __syncthreads();
    }
    if (t < NB_SCAN) g_bsum[t] = sh[t] - v;
}

__global__ void scan3_kernel() {
    int i = blockIdx.x * blockDim.x + threadIdx.x;
    if (i < NN) g_row[i] += g_bsum[i >> 10];
    if (i == 0) g_row[NN] = EE;
}

__global__ void scatter_kernel(const int* __restrict__ ei, const float* __restrict__ ew) {
    int e = blockIdx.x * blockDim.x + threadIdx.x;
    if (e < EE) {
        int src = ei[e];
        int dst = ei[EE + e];
        int pos = g_row[dst] + atomicAdd(&g_cnt[dst], 1);
        g_edge[pos] = make_float2(__int_as_float(src), ew[e]);
    }
}

// ---------------- prep MLP: x[N,16] -> h[N,64] -------------------------------
__global__ void prep_kernel(const float* __restrict__ x,
                            const float* __restrict__ Wpin, const float* __restrict__ bpin,
                            const float* __restrict__ Wph,  const float* __restrict__ bph) {
    __shared__ float sWin[16 * 64];
    __shared__ float sWh[64 * 64];
    __shared__ float sb0[64], sb1[64];
    __shared__ float xs[8][16 * ZP];
    __shared__ float zs[8][64 * ZP];

    int tid = threadIdx.x;
    for (int i = tid; i < 16 * 64; i += 256) sWin[i] = Wpin[i];
    for (int i = tid; i < 64 * 64; i += 256) sWh[i]  = Wph[i];
    if (tid < 64) { sb0[tid] = bpin[tid]; sb1[tid] = bph[tid]; }
    __syncthreads();

    int warp = tid >> 5, lane = tid & 31;
    const float2* sWinV = (const float2*)sWin;
    const float2* sWhV  = (const float2*)sWh;
    float2* hout2 = (float2*)g_hA;
    const float2 b0 = ((const float2*)sb0)[lane];
    const float2 b1 = ((const float2*)sb1)[lane];

    int grp;
    if (lane == 0) grp = atomicAdd(&g_work[0], 1);
    grp = __shfl_sync(0xffffffffu, grp, 0);
    while (grp < NGROUPS) {
        int nbase = grp * 8;
        // stage x transposed: xs[f][n]
        float4 v = *(const float4*)&x[nbase * 16 + 4 * lane];
        int nd = lane >> 2, fb = (lane & 3) * 4;
        xs[warp][(fb + 0) * ZP + nd] = v.x;
        xs[warp][(fb + 1) * ZP + nd] = v.y;
        xs[warp][(fb + 2) * ZP + nd] = v.z;
        xs[warp][(fb + 3) * ZP + nd] = v.w;
        __syncwarp();
        // layer 0: 16 -> 64
        u64 a0[4], a1[4];
        #pragma unroll
        for (int p = 0; p < 4; p++) { a0[p] = pk(b0.x, b0.x); a1[p] = pk(b0.y, b0.y); }
        #pragma unroll
        for (int k = 0; k < 16; k++) {
            float2 wv = sWinV[k * 32 + lane];
            u64 wxx = pk(wv.x, wv.x), wyy = pk(wv.y, wv.y);
            #pragma unroll
            for (int p = 0; p < 4; p++) {
                u64 zp = *(const u64*)&xs[warp][k * ZP + 2 * p];
                a0[p] = ffma2(zp, wxx, a0[p]);
                a1[p] = ffma2(zp, wyy, a1[p]);
            }
        }
        __syncwarp();
        #pragma unroll
        for (int p = 0; p < 4; p++) {
            float x0, x1, y0, y1;
            upk(a0[p], x0, x1); upk(a1[p], y0, y1);
            *(u64*)&zs[warp][(2 * lane) * ZP + 2 * p]     = pk(lrelu(x0), lrelu(x1));
            *(u64*)&zs[warp][(2 * lane + 1) * ZP + 2 * p] = pk(lrelu(y0), lrelu(y1));
        }
        __syncwarp();
        // layer 1: 64 -> 64 + tanh
        u64 c0[4], c1[4];
        #pragma unroll
        for (int p = 0; p < 4; p++) { c0[p] = pk(b1.x, b1.x); c1[p] = pk(b1.y, b1.y); }
        #pragma unroll 16
        for (int k = 0; k < 64; k++) {
            float2 wv = sWhV[k * 32 + lane];
            u64 wxx = pk(wv.x, wv.x), wyy = pk(wv.y, wv.y);
            #pragma unroll
            for (int p = 0; p < 4; p++) {
                u64 zp = *(const u64*)&zs[warp][k * ZP + 2 * p];
                c0[p] = ffma2(zp, wxx, c0[p]);
                c1[p] = ffma2(zp, wyy, c1[p]);
            }
        }
        #pragma unroll
        for (int p = 0; p < 4; p++) {
            float x0, x1, y0, y1;
            upk(c0[p], x0, x1); upk(c1[p], y0, y1);
            hout2[(nbase + 2 * p) * 32 + lane]     = make_float2(tanhf(x0), tanhf(y0));
            hout2[(nbase + 2 * p + 1) * 32 + lane] = make_float2(tanhf(x1), tanhf(y1));
        }
        __syncwarp();
        if (lane == 0) grp = atomicAdd(&g_work[0], 1);
        grp = __shfl_sync(0xffffffffu, grp, 0);
    }
}

// ---------------- fused GINEConv ---------------------------------------------
__global__ void conv_kernel(int dir, int wsel,
                            const float* __restrict__ We_row, const float* __restrict__ be,
                            const float* __restrict__ Wm0,  const float* __restrict__ bm0,
                            const float* __restrict__ Wm1,  const float* __restrict__ bm1) {
    const float*  hin  = dir ? g_hB : g_hA;
    float*        hout = dir ? g_hA : g_hB;
    const float4* __restrict__ hin4  = (const float4*)hin;
    float2*       __restrict__ hout2 = (float2*)hout;

    __shared__ float sWm0[64 * 64];
    __shared__ float sWm1[64 * 64];
    __shared__ float sWe[64], sbe[64], sbm0[64], sbm1[64];
    __shared__ float zs[8][64 * ZP];

    int tid = threadIdx.x;
    for (int i = tid; i < 64 * 64; i += 256) { sWm0[i] = Wm0[i]; sWm1[i] = Wm1[i]; }
    if (tid < 64) { sWe[tid] = We_row[tid]; sbe[tid] = be[tid];
                    sbm0[tid] = bm0[tid];   sbm1[tid] = bm1[tid]; }
    __syncthreads();

    int warp = tid >> 5, lane = tid & 31;
    int u16 = lane >> 4, c = lane & 15;
    const float2* sWm0v = (const float2*)sWm0;
    const float2* sWm1v = (const float2*)sWm1;
    const float4 we4 = *(const float4*)&sWe[4 * c];
    const float4 be4 = *(const float4*)&sbe[4 * c];
    const float2 b0  = ((const float2*)sbm0)[lane];
    const float2 b1  = ((const float2*)sbm1)[lane];

    int grp;
    if (lane == 0) grp = atomicAdd(&g_work[wsel], 1);
    grp = __shfl_sync(0xffffffffu, grp, 0);
    while (grp < NGROUPS) {
        int nbase = grp * 8;
        // ---- aggregation for 8 nodes, write z transposed ----
        #pragma unroll 1
        for (int n = 0; n < 8; n++) {
            int node = nbase + n;
            int rs = g_row[node];
            int re = g_row[node + 1];
            float4 acc = make_float4(0.f, 0.f, 0.f, 0.f);
            for (int base = rs; base < re; base += 32) {
                int m = re - base; if (m > 32) m = 32;
                float2 ed = make_float2(0.f, 0.f);
                if (base + lane < re) ed = __ldg(&g_edge[base + lane]);
                int   esrc = __float_as_int(ed.x);
                float ewt  = ed.y;
                int i = 0;
                for (; i + 4 <= m; i += 4) {
                    int   sA = __shfl_sync(0xffffffffu, esrc, i + u16);
                    float wA = __shfl_sync(0xffffffffu, ewt,  i + u16);
                    int   sB = __shfl_sync(0xffffffffu, esrc, i + 2 + u16);
                    float wB = __shfl_sync(0xffffffffu, ewt,  i + 2 + u16);
                    float4 hA = __ldg(&hin4[sA * 16 + c]);
                    float4 hB = __ldg(&hin4[sB * 16 + c]);
                    acc.x += fmaxf(hA.x + fmaf(wA, we4.x, be4.x), 0.f);
                    acc.y += fmaxf(hA.y + fmaf(wA, we4.y, be4.y), 0.f);
                    acc.z += fmaxf(hA.z + fmaf(wA, we4.z, be4.z), 0.f);
                    acc.w += fmaxf(hA.w + fmaf(wA, we4.w, be4.w), 0.f);
                    acc.x += fmaxf(hB.x + fmaf(wB, we4.x, be4.x), 0.f);
                    acc.y += fmaxf(hB.y + fmaf(wB, we4.y, be4.y), 0.f);
                    acc.z += fmaxf(hB.z + fmaf(wB, we4.z, be4.z), 0.f);
                    acc.w += fmaxf(hB.w + fmaf(wB, we4.w, be4.w), 0.f);
                }
                for (; i < m; i += 2) {
                    int idx = i + u16;
                    int   s = __shfl_sync(0xffffffffu, esrc, idx & 31);
                    float w = __shfl_sync(0xffffffffu, ewt,  idx & 31);
                    if (idx < m) {
                        float4 h = __ldg(&hin4[s * 16 + c]);
                        acc.x += fmaxf(h.x + fmaf(w, we4.x, be4.x), 0.f);
                        acc.y += fmaxf(h.y + fmaf(w, we4.y, be4.y), 0.f);
                        acc.z += fmaxf(h.z + fmaf(w, we4.z, be4.z), 0.f);
                        acc.w += fmaxf(h.w + fmaf(w, we4.w, be4.w), 0.f);
                    }
                }
            }
            acc.x += __shfl_xor_sync(0xffffffffu, acc.x, 16);
            acc.y += __shfl_xor_sync(0xffffffffu, acc.y, 16);
            acc.z += __shfl_xor_sync(0xffffffffu, acc.z, 16);
            acc.w += __shfl_xor_sync(0xffffffffu, acc.w, 16);
            if (u16 == 0) {
                float4 hs = __ldg(&hin4[node * 16 + c]);
                zs[warp][(4 * c + 0) * ZP + n] = acc.x + hs.x;
                zs[warp][(4 * c + 1) * ZP + n] = acc.y + hs.y;
                zs[warp][(4 * c + 2) * ZP + n] = acc.z + hs.z;
                zs[warp][(4 * c + 3) * ZP + n] = acc.w + hs.w;
            }
        }
        __syncwarp();

        // ---- MLP layer 0 (64->64) + LeakyReLU ----
        u64 a0[4], a1[4];
        #pragma unroll
        for (int p = 0; p < 4; p++) { a0[p] = pk(b0.x, b0.x); a1[p] = pk(b0.y, b0.y); }
        #pragma unroll 16
        for (int k = 0; k < 64; k++) {
            float2 wv = sWm0v[k * 32 + lane];
            u64 wxx = pk(wv.x, wv.x), wyy = pk(wv.y, wv.y);
            #pragma unroll
            for (int p = 0; p < 4; p++) {
                u64 zp = *(const u64*)&zs[warp][k * ZP + 2 * p];
                a0[p] = ffma2(zp, wxx, a0[p]);
                a1[p] = ffma2(zp, wyy, a1[p]);
            }
        }
        __syncwarp();
        #pragma unroll
        for (int p = 0; p < 4; p++) {
            float x0, x1, y0, y1;
            upk(a0[p], x0, x1); upk(a1[p], y0, y1);
            *(u64*)&zs[warp][(2 * lane) * ZP + 2 * p]     = pk(lrelu(x0), lrelu(x1));
            *(u64*)&zs[warp][(2 * lane + 1) * ZP + 2 * p] = pk(lrelu(y0), lrelu(y1));
        }
        __syncwarp();

        // ---- MLP layer 1 (64->64) + tanh ----
        u64 c0[4], c1[4];
        #pragma unroll
        for (int p = 0; p < 4; p++) { c0[p] = pk(b1.x, b1.x); c1[p] = pk(b1.y, b1.y); }
        #pragma unroll 16
        for (int k = 0; k < 64; k++) {
            float2 wv = sWm1v[k * 32 + lane];
            u64 wxx = pk(wv.x, wv.x), wyy = pk(wv.y, wv.y);
            #pragma unroll
            for (int p = 0; p < 4; p++) {
                u64 zp = *(const u64*)&zs[warp][k * ZP + 2 * p];
                c0[p] = ffma2(zp, wxx, c0[p]);
                c1[p] = ffma2(zp, wyy, c1[p]);
            }
        }
        #pragma unroll
        for (int p = 0; p < 4; p++) {
            float x0, x1, y0, y1;
            upk(c0[p], x0, x1); upk(c1[p], y0, y1);
            hout2[(nbase + 2 * p) * 32 + lane]     = make_float2(tanhf(x0), tanhf(y0));
            hout2[(nbase + 2 * p + 1) * 32 + lane] = make_float2(tanhf(x1), tanhf(y1));
        }
        __syncwarp();
        if (lane == 0) grp = atomicAdd(&g_work[wsel], 1);
        grp = __shfl_sync(0xffffffffu, grp, 0);
    }
}

// ---------------- post MLP: h[N,64] -> out[N,32] ------------------------------
__global__ void post_kernel(const float* __restrict__ Wq0, const float* __restrict__ bq0,
                            const float* __restrict__ Wq1, const float* __restrict__ bq1,
                            float* __restrict__ out) {
    __shared__ float sW0[64 * 64];
    __shared__ float sW1[64 * 32];
    __shared__ float sb0[64], sb1[32];
    __shared__ float zs[8][64 * ZP];

    const float2* __restrict__ hin2 = (const float2*)g_hB;   // after conv2

    int tid = threadIdx.x;
    for (int i = tid; i < 64 * 64; i += 256) sW0[i] = Wq0[i];
    for (int i = tid; i < 64 * 32; i += 256) sW1[i] = Wq1[i];
    if (tid < 64) sb0[tid] = bq0[tid];
    if (tid < 32) sb1[tid] = bq1[tid];
    __syncthreads();

    int warp = tid >> 5, lane = tid & 31;
    const float2* sW0v = (const float2*)sW0;
    const float2 b0 = ((const float2*)sb0)[lane];
    const float  bL = sb1[lane];

    int grp;
    if (lane == 0) grp = atomicAdd(&g_work[4], 1);
    grp = __shfl_sync(0xffffffffu, grp, 0);
    while (grp < NGROUPS) {
        int nbase = grp * 8;
        // stage input transposed
        #pragma unroll
        for (int n = 0; n < 8; n++) {
            float2 v = hin2[(nbase + n) * 32 + lane];
            zs[warp][(2 * lane) * ZP + n]     = v.x;
            zs[warp][(2 * lane + 1) * ZP + n] = v.y;
        }
        __syncwarp();
        // layer 0: 64 -> 64 + lrelu
        u64 a0[4], a1[4];
        #pragma unroll
        for (int p = 0; p < 4; p++) { a0[p] = pk(b0.x, b0.x); a1[p] = pk(b0.y, b0.y); }
        #pragma unroll 16
        for (int k = 0; k < 64; k++) {
            float2 wv = sW0v[k * 32 + lane];
            u64 wxx = pk(wv.x, wv.x), wyy = pk(wv.y, wv.y);
            #pragma unroll
            for (int p = 0; p < 4; p++) {
                u64 zp = *(const u64*)&zs[warp][k * ZP + 2 * p];
                a0[p] = ffma2(zp, wxx, a0[p]);
                a1[p] = ffma2(zp, wyy, a1[p]);
            }
        }
        __syncwarp();
        #pragma unroll
        for (int p = 0; p < 4; p++) {
            float x0, x1, y0, y1;
            upk(a0[p], x0, x1); upk(a1[p], y0, y1);
            *(u64*)&zs[warp][(2 * lane) * ZP + 2 * p]     = pk(lrelu(x0), lrelu(x1));
            *(u64*)&zs[warp][(2 * lane + 1) * ZP + 2 * p] = pk(lrelu(y0), lrelu(y1));
        }
        __syncwarp();
        // layer 1: 64 -> 32 + tanh (lane owns output feature = lane)
        u64 c0[4];
        #pragma unroll
        for (int p = 0; p < 4; p++) c0[p] = pk(bL, bL);
        #pragma unroll 16
        for (int k = 0; k < 64; k++) {
            float w = sW1[k * 32 + lane];
            u64 www = pk(w, w);
            #pragma unroll
            for (int p = 0; p < 4; p++) {
                u64 zp = *(const u64*)&zs[warp][k * ZP + 2 * p];
                c0[p] = ffma2(zp, www, c0[p]);
            }
        }
        #pragma unroll
        for (int p = 0; p < 4; p++) {
            float x0, x1;
            upk(c0[p], x0, x1);
            out[(nbase + 2 * p) * 32 + lane]     = tanhf(x0);
            out[(nbase + 2 * p + 1) * 32 + lane] = tanhf(x1);
        }
        __syncwarp();
        if (lane == 0) grp = atomicAdd(&g_work[4], 1);
        grp = __shfl_sync(0xffffffffu, grp, 0);
    }
}

// ---------------- launch -------------------------------------------------------
extern "C" void kernel_launch(void* const* d_in, const int* in_sizes, int n_in,
                              void* d_out, int out_size) {
    const float* x     = (const float*)d_in[0];
    const int*   ei    = (const int*)  d_in[1];
    const float* ew    = (const float*)d_in[2];
    const float* Wp_in = (const float*)d_in[3];
    const float* bp_in = (const float*)d_in[4];
    const float* Wp_h  = (const float*)d_in[5];
    const float* bp_h  = (const float*)d_in[6];
    const float* We    = (const float*)d_in[7];
    const float* be    = (const float*)d_in[8];
    const float* Wm0   = (const float*)d_in[9];
    const float* bm0   = (const float*)d_in[10];
    const float* Wm1   = (const float*)d_in[11];
    const float* bm1   = (const float*)d_in[12];
    const float* Wq0   = (const float*)d_in[13];
    const float* bq0   = (const float*)d_in[14];
    const float* Wq1   = (const float*)d_in[15];
    const float* bq1   = (const float*)d_in[16];
    float* out = (float*)d_out;

    // CSR build
    zero_kernel<<<(NN + 255) / 256, 256>>>();
    hist_kernel<<<(EE + 255) / 256, 256>>>(ei);
    scan1_kernel<<<NB_SCAN, 1024>>>();
    scan2_kernel<<<1, 64>>>();
    scan3_kernel<<<(NN + 255) / 256, 256>>>();
    scatter_kernel<<<(EE + 255) / 256, 256>>>(ei, ew);

    // prep MLP -> g_hA
    prep_kernel<<<592, 256>>>(x, Wp_in, bp_in, Wp_h, bp_h);

    // 3 GINEConv layers, ping-pong A<->B
    conv_kernel<<<592, 256>>>(0, 1, We + 0 * 64, be + 0 * 64,
                              Wm0 + 0 * 4096, bm0 + 0 * 64,
                              Wm1 + 0 * 4096, bm1 + 0 * 64);   // A -> B
    conv_kernel<<<592, 256>>>(1, 2, We + 1 * 64, be + 1 * 64,
                              Wm0 + 1 * 4096, bm0 + 1 * 64,
                              Wm1 + 1 * 4096, bm1 + 1 * 64);   // B -> A
    conv_kernel<<<592, 256>>>(0, 3, We + 2 * 64, be + 2 * 64,
                              Wm0 + 2 * 4096, bm0 + 2 * 64,
                              Wm1 + 2 * 4096, bm1 + 2 * 64);   // A -> B

    // post MLP -> out
    post_kernel<<<592, 256>>>(Wq0, bq0, Wq1, bq1, out);
}